// round 3
// baseline (speedup 1.0000x reference)
#include <cuda_runtime.h>
#include <cstdint>

#define N_NODES 50000
#define FIN 512
#define FOUT 128

// Scratch for pre_sup = x @ W  (25.6 MB, static device global: no allocation)
__device__ float g_pre[(size_t)N_NODES * FOUT];

// ---------------------------------------------------------------------------
// Zero the output buffer (it arrives poisoned with 0xAA)
// ---------------------------------------------------------------------------
__global__ void zero_kernel(float4* __restrict__ out, int n4) {
    int i = blockIdx.x * blockDim.x + threadIdx.x;
    if (i < n4) out[i] = make_float4(0.f, 0.f, 0.f, 0.f);
}

// ---------------------------------------------------------------------------
// SGEMM: C[M, FOUT] = A[M, FIN] * B[FIN, FOUT]; M=50000, FIN=512, FOUT=128
// Block tile 128x128 (full FOUT), K-step 8, 256 threads, 8x8 per-thread tile.
// ---------------------------------------------------------------------------
#define TM 128
#define TK 8

__global__ __launch_bounds__(256) void gemm_kernel(const float* __restrict__ A,
                                                   const float* __restrict__ B) {
    __shared__ float As[TK][TM + 4];   // +4 pad kills store conflicts, keeps 16B align
    __shared__ float Bs[TK][FOUT];

    const int tid = threadIdx.x;
    const int tx = tid & 15;           // 16 col groups of 8
    const int ty = tid >> 4;           // 16 row groups of 8
    const int block_row = blockIdx.x * TM;

    float acc[8][8];
#pragma unroll
    for (int i = 0; i < 8; i++)
#pragma unroll
        for (int j = 0; j < 8; j++) acc[i][j] = 0.f;

    // A-tile loader mapping: each thread loads one float4 (half a K-slice row)
    const int ar = tid >> 1;
    const int ak = (tid & 1) * 4;
    const int arow = block_row + ar;
    const bool avalid = (arow < N_NODES);
    const float* aptr = A + (size_t)arow * FIN + ak;

    for (int k0 = 0; k0 < FIN; k0 += TK) {
        float4 av = make_float4(0.f, 0.f, 0.f, 0.f);
        if (avalid) av = *(const float4*)(aptr + k0);
        As[ak + 0][ar] = av.x;
        As[ak + 1][ar] = av.y;
        As[ak + 2][ar] = av.z;
        As[ak + 3][ar] = av.w;

#pragma unroll
        for (int j = 0; j < 4; j++) {
            int idx = tid + j * 256;      // 0..1023
            int bk = idx >> 7;            // 0..7
            int bn = idx & 127;           // 0..127
            Bs[bk][bn] = B[(size_t)(k0 + bk) * FOUT + bn];
        }
        __syncthreads();

#pragma unroll
        for (int kk = 0; kk < TK; kk++) {
            float4 a0 = *(const float4*)&As[kk][ty * 8];
            float4 a1 = *(const float4*)&As[kk][ty * 8 + 4];
            float4 b0 = *(const float4*)&Bs[kk][tx * 8];
            float4 b1 = *(const float4*)&Bs[kk][tx * 8 + 4];
            float a[8] = {a0.x, a0.y, a0.z, a0.w, a1.x, a1.y, a1.z, a1.w};
            float b[8] = {b0.x, b0.y, b0.z, b0.w, b1.x, b1.y, b1.z, b1.w};
#pragma unroll
            for (int i = 0; i < 8; i++)
#pragma unroll
                for (int j = 0; j < 8; j++) acc[i][j] += a[i] * b[j];
        }
        __syncthreads();
    }

#pragma unroll
    for (int i = 0; i < 8; i++) {
        int r = block_row + ty * 8 + i;
        if (r < N_NODES) {
            float* crow = g_pre + (size_t)r * FOUT + tx * 8;
            *(float4*)(crow)     = make_float4(acc[i][0], acc[i][1], acc[i][2], acc[i][3]);
            *(float4*)(crow + 4) = make_float4(acc[i][4], acc[i][5], acc[i][6], acc[i][7]);
        }
    }
}

// ---------------------------------------------------------------------------
// SPMM scatter: out[row] += val * pre_sup[col], one warp per edge.
// Indices are int32 (harness downcasts int64 inputs to int32).
// Lane l handles floats [4l, 4l+4): coalesced 512B gather + red.global.v4.f32.
// ---------------------------------------------------------------------------
__global__ __launch_bounds__(256) void spmm_kernel(const int* __restrict__ idx,
                                                   const float* __restrict__ vals,
                                                   float* __restrict__ out, int E) {
    int warp = (blockIdx.x * blockDim.x + threadIdx.x) >> 5;
    int lane = threadIdx.x & 31;
    if (warp >= E) return;

    int row = idx[warp];       // idx[0][e]
    int col = idx[E + warp];   // idx[1][e]
    // Defensive bounds guard: turns a dtype misread into a wrong answer
    // (visible rel_err) instead of an illegal memory access.
    if ((unsigned)row >= N_NODES || (unsigned)col >= N_NODES) return;
    float v = vals[warp];

    const float4* src = (const float4*)(g_pre + (size_t)col * FOUT);
    float4 m = src[lane];
    m.x *= v; m.y *= v; m.z *= v; m.w *= v;

    float* dst = out + (size_t)row * FOUT + lane * 4;
    asm volatile("red.global.add.v4.f32 [%0], {%1, %2, %3, %4};"
                 :: "l"(dst), "f"(m.x), "f"(m.y), "f"(m.z), "f"(m.w)
                 : "memory");
}

// ---------------------------------------------------------------------------
// Epilogue: out = relu(out + bias), applied to both [N, FOUT] branches.
// ---------------------------------------------------------------------------
__global__ void bias_relu_kernel(float4* __restrict__ out,
                                 const float4* __restrict__ bias4, int n4) {
    int i = blockIdx.x * blockDim.x + threadIdx.x;
    if (i >= n4) return;
    float4 v = out[i];
    float4 b = bias4[i & 31];   // FOUT = 128 floats = 32 float4
    v.x = fmaxf(v.x + b.x, 0.f);
    v.y = fmaxf(v.y + b.y, 0.f);
    v.z = fmaxf(v.z + b.z, 0.f);
    v.w = fmaxf(v.w + b.w, 0.f);
    out[i] = v;
}

// ---------------------------------------------------------------------------
// Launch: zero -> gemm -> spmm(support) -> spmm(ori) -> bias+relu
// ---------------------------------------------------------------------------
extern "C" void kernel_launch(void* const* d_in, const int* in_sizes, int n_in,
                              void* d_out, int out_size) {
    const float* x     = (const float*)d_in[0];
    const int*   sidx  = (const int*)d_in[1];
    const float* svals = (const float*)d_in[2];
    const int*   oidx  = (const int*)d_in[3];
    const float* ovals = (const float*)d_in[4];
    const float* W     = (const float*)d_in[5];
    const float* bias  = (const float*)d_in[6];
    float* out = (float*)d_out;

    const int E = in_sizes[2];               // support_vals element count
    const int n4 = out_size / 4;             // float4 count of output

    zero_kernel<<<(n4 + 255) / 256, 256>>>((float4*)out, n4);

    gemm_kernel<<<(N_NODES + TM - 1) / TM, 256>>>(x, W);

    // branch 0: support, branch 1: ori_support (stacked [2, N, FOUT])
    int spmm_blocks = (E + 7) / 8;           // 8 warps (edges) per 256-thread block
    spmm_kernel<<<spmm_blocks, 256>>>(sidx, svals, out, E);
    spmm_kernel<<<spmm_blocks, 256>>>(oidx, ovals, out + (size_t)N_NODES * FOUT, E);

    bias_relu_kernel<<<(n4 + 255) / 256, 256>>>((float4*)out, (const float4*)bias, n4);
}

// round 8
// speedup vs baseline: 1.6463x; 1.6463x over previous
#include <cuda_runtime.h>
#include <cstdint>

#define N_NODES 50000
#define FIN 512
#define FOUT 128

// Scratch for pre_sup = x @ W  (25.6 MB, static device global: no allocation)
__device__ float g_pre[(size_t)N_NODES * FOUT];

// ---------------------------------------------------------------------------
// Zero the output buffer (it arrives poisoned with 0xAA)
// ---------------------------------------------------------------------------
__global__ void zero_kernel(float4* __restrict__ out, int n4) {
    int i = blockIdx.x * blockDim.x + threadIdx.x;
    if (i < n4) out[i] = make_float4(0.f, 0.f, 0.f, 0.f);
}

// ---------------------------------------------------------------------------
// tf32 helpers
// ---------------------------------------------------------------------------
__device__ __forceinline__ uint32_t f2tf32(float f) {
    uint32_t u;
    asm("cvt.rna.tf32.f32 %0, %1;" : "=r"(u) : "f"(f));
    return u;
}

__device__ __forceinline__ void mma_tf32(float* d, const uint32_t* a, const uint32_t* b) {
    asm("mma.sync.aligned.m16n8k8.row.col.f32.tf32.tf32.f32 "
        "{%0,%1,%2,%3}, {%4,%5,%6,%7}, {%8,%9}, {%0,%1,%2,%3};"
        : "+f"(d[0]), "+f"(d[1]), "+f"(d[2]), "+f"(d[3])
        : "r"(a[0]), "r"(a[1]), "r"(a[2]), "r"(a[3]), "r"(b[0]), "r"(b[1]));
}

// ---------------------------------------------------------------------------
// tf32 GEMM: g_pre[M, FOUT] = A[M, FIN] * B[FIN, FOUT]
// Block tile M=128 x N=128, K-chunk 32, 256 threads = 8 warps (4M x 2N).
// Warp tile 32(M) x 64(N): 2 m-tiles x 8 n-tiles of m16n8k8.
// As[m][k] stride 36 -> frag-read bank (4m+k)%32, conflict-free.
// Bs[k][n] stride 136 -> frag-read bank (8k+n)%32, conflict-free.
// ---------------------------------------------------------------------------
#define GM 128
#define GK 32
#define AS_STR 36
#define BS_STR 136

__global__ __launch_bounds__(256, 2) void gemm_tf32_kernel(const float* __restrict__ A,
                                                           const float* __restrict__ B) {
    __shared__ uint32_t As[GM][AS_STR];   // [m][k] tf32 bits
    __shared__ uint32_t Bs[GK][BS_STR];   // [k][n] tf32 bits

    const int tid = threadIdx.x;
    const int w = tid >> 5, l = tid & 31;
    const int wm = (w >> 1) * 32;          // warp M offset (4 warps over M)
    const int wn = (w & 1) * 64;           // warp N offset (2 warps over N)
    const int g = l >> 2, tg = l & 3;      // groupID, thread-in-group
    const int block_row = blockIdx.x * GM;

    float acc[2][8][4];
#pragma unroll
    for (int mi = 0; mi < 2; mi++)
#pragma unroll
        for (int ni = 0; ni < 8; ni++)
#pragma unroll
            for (int q = 0; q < 4; q++) acc[mi][ni][q] = 0.f;

    // A loader: thread handles row m=tid>>1, k-half (tid&1)*16 (4 float4s)
    const int am = tid >> 1;
    const int akh = (tid & 1) * 16;
    const int arow = block_row + am;
    const bool aval = (arow < N_NODES);
    const float* aptr = A + (size_t)arow * FIN + akh;
    // B loader: thread handles k-row tid>>3, n-range (tid&7)*16 (4 float4s)
    const int bk = tid >> 3;
    const int bn = (tid & 7) * 16;
    const float* bptr = B + (size_t)bk * FOUT + bn;

    for (int k0 = 0; k0 < FIN; k0 += GK) {
#pragma unroll
        for (int j = 0; j < 4; j++) {
            float4 av = make_float4(0.f, 0.f, 0.f, 0.f);
            if (aval) av = *(const float4*)(aptr + k0 + j * 4);
            uint4 tv = make_uint4(f2tf32(av.x), f2tf32(av.y), f2tf32(av.z), f2tf32(av.w));
            *(uint4*)&As[am][akh + j * 4] = tv;   // stride 144B: 16B-aligned
        }
#pragma unroll
        for (int j = 0; j < 4; j++) {
            float4 bv = *(const float4*)(bptr + (size_t)k0 * FOUT + j * 4);
            uint4 tv = make_uint4(f2tf32(bv.x), f2tf32(bv.y), f2tf32(bv.z), f2tf32(bv.w));
            *(uint4*)&Bs[bk][bn + j * 4] = tv;    // stride 544B: 16B-aligned
        }
        __syncthreads();

#pragma unroll
        for (int ks = 0; ks < 4; ks++) {
            const int kb = ks * 8;
            uint32_t afr[2][4], bfr[8][2];
#pragma unroll
            for (int mi = 0; mi < 2; mi++) {
                const int m = wm + mi * 16;
                afr[mi][0] = As[m + g][kb + tg];
                afr[mi][1] = As[m + g + 8][kb + tg];
                afr[mi][2] = As[m + g][kb + tg + 4];
                afr[mi][3] = As[m + g + 8][kb + tg + 4];
            }
#pragma unroll
            for (int ni = 0; ni < 8; ni++) {
                const int n = wn + ni * 8 + g;
                bfr[ni][0] = Bs[kb + tg][n];
                bfr[ni][1] = Bs[kb + tg + 4][n];
            }
#pragma unroll
            for (int mi = 0; mi < 2; mi++)
#pragma unroll
                for (int ni = 0; ni < 8; ni++)
                    mma_tf32(acc[mi][ni], afr[mi], bfr[ni]);
        }
        __syncthreads();
    }

#pragma unroll
    for (int mi = 0; mi < 2; mi++) {
        const int r0 = block_row + wm + mi * 16 + g;
#pragma unroll
        for (int ni = 0; ni < 8; ni++) {
            const int c = wn + ni * 8 + tg * 2;
            if (r0 < N_NODES)
                *(float2*)(g_pre + (size_t)r0 * FOUT + c) =
                    make_float2(acc[mi][ni][0], acc[mi][ni][1]);
            if (r0 + 8 < N_NODES)
                *(float2*)(g_pre + (size_t)(r0 + 8) * FOUT + c) =
                    make_float2(acc[mi][ni][2], acc[mi][ni][3]);
        }
    }
}

// ---------------------------------------------------------------------------
// Fused SPMM scatter, both branches (blockIdx.y), 4 edges per warp for MLP.
// out[row] += val * pre_sup[col]; lane l handles floats [4l, 4l+4).
// Indices are int32 (harness downcasts int64 inputs to int32).
// ---------------------------------------------------------------------------
__global__ __launch_bounds__(256) void spmm4_kernel(const int* __restrict__ idx0,
                                                    const float* __restrict__ v0,
                                                    const int* __restrict__ idx1,
                                                    const float* __restrict__ v1,
                                                    float* __restrict__ out, int E) {
    const int* idx = blockIdx.y ? idx1 : idx0;
    const float* vals = blockIdx.y ? v1 : v0;
    float* o = out + (size_t)blockIdx.y * N_NODES * FOUT;

    int warp = (blockIdx.x * blockDim.x + threadIdx.x) >> 5;
    int lane = threadIdx.x & 31;
    int base = warp * 4;
    if (base >= E) return;

    int rows[4], cols[4];
    float v[4];
    bool ok[4];
#pragma unroll
    for (int e = 0; e < 4; e++) {
        int i = base + e;
        ok[e] = (i < E);
        if (ok[e]) {
            rows[e] = idx[i];
            cols[e] = idx[E + i];
            v[e] = vals[i];
            if ((unsigned)rows[e] >= N_NODES || (unsigned)cols[e] >= N_NODES) ok[e] = false;
        }
    }

    float4 m[4];
#pragma unroll
    for (int e = 0; e < 4; e++)
        if (ok[e])
            m[e] = *((const float4*)(g_pre + (size_t)cols[e] * FOUT) + lane);

#pragma unroll
    for (int e = 0; e < 4; e++) {
        if (!ok[e]) continue;
        float4 t = m[e];
        t.x *= v[e]; t.y *= v[e]; t.z *= v[e]; t.w *= v[e];
        float* dst = o + (size_t)rows[e] * FOUT + lane * 4;
        asm volatile("red.global.add.v4.f32 [%0], {%1, %2, %3, %4};"
                     :: "l"(dst), "f"(t.x), "f"(t.y), "f"(t.z), "f"(t.w)
                     : "memory");
    }
}

// ---------------------------------------------------------------------------
// Epilogue: out = relu(out + bias), applied to both [N, FOUT] branches.
// ---------------------------------------------------------------------------
__global__ void bias_relu_kernel(float4* __restrict__ out,
                                 const float4* __restrict__ bias4, int n4) {
    int i = blockIdx.x * blockDim.x + threadIdx.x;
    if (i >= n4) return;
    float4 v = out[i];
    float4 b = bias4[i & 31];   // FOUT = 128 floats = 32 float4
    v.x = fmaxf(v.x + b.x, 0.f);
    v.y = fmaxf(v.y + b.y, 0.f);
    v.z = fmaxf(v.z + b.z, 0.f);
    v.w = fmaxf(v.w + b.w, 0.f);
    out[i] = v;
}

// ---------------------------------------------------------------------------
// Launch: zero -> gemm(tf32) -> fused spmm x2 -> bias+relu
// ---------------------------------------------------------------------------
extern "C" void kernel_launch(void* const* d_in, const int* in_sizes, int n_in,
                              void* d_out, int out_size) {
    const float* x     = (const float*)d_in[0];
    const int*   sidx  = (const int*)d_in[1];
    const float* svals = (const float*)d_in[2];
    const int*   oidx  = (const int*)d_in[3];
    const float* ovals = (const float*)d_in[4];
    const float* W     = (const float*)d_in[5];
    const float* bias  = (const float*)d_in[6];
    float* out = (float*)d_out;

    const int E = in_sizes[2];               // support_vals element count
    const int n4 = out_size / 4;             // float4 count of output

    zero_kernel<<<(n4 + 255) / 256, 256>>>((float4*)out, n4);

    gemm_tf32_kernel<<<(N_NODES + GM - 1) / GM, 256>>>(x, W);

    // 4 edges/warp, 8 warps/block, grid.y selects branch
    dim3 sgrid((E + 31) / 32, 2);
    spmm4_kernel<<<sgrid, 256>>>(sidx, svals, oidx, ovals, out, E);

    bias_relu_kernel<<<(n4 + 255) / 256, 256>>>((float4*)out, (const float4*)bias, n4);
}

// round 10
// speedup vs baseline: 1.6724x; 1.0158x over previous
#include <cuda_runtime.h>
#include <cstdint>

#define N_NODES 50000
#define FIN 512
#define FOUT 128
#define MAXE 1000000

// Static device scratch (no allocation anywhere):
__device__ float g_pre[(size_t)N_NODES * FOUT];          // 25.6 MB
__device__ int   g_counts[2][N_NODES];                   // histogram
__device__ int   g_rowstart[2][N_NODES + 1];             // CSR offsets
__device__ int   g_cursor[2][N_NODES];                   // scatter cursors
__device__ int   g_colsorted[2][MAXE];                   // 8 MB
__device__ float g_valsorted[2][MAXE];                   // 8 MB

// ---------------------------------------------------------------------------
// tf32 helpers
// ---------------------------------------------------------------------------
__device__ __forceinline__ uint32_t f2tf32(float f) {
    uint32_t u;
    asm("cvt.rna.tf32.f32 %0, %1;" : "=r"(u) : "f"(f));
    return u;
}

__device__ __forceinline__ void mma_tf32(float* d, const uint32_t* a, const uint32_t* b) {
    asm("mma.sync.aligned.m16n8k8.row.col.f32.tf32.tf32.f32 "
        "{%0,%1,%2,%3}, {%4,%5,%6,%7}, {%8,%9}, {%0,%1,%2,%3};"
        : "+f"(d[0]), "+f"(d[1]), "+f"(d[2]), "+f"(d[3])
        : "r"(a[0]), "r"(a[1]), "r"(a[2]), "r"(a[3]), "r"(b[0]), "r"(b[1]));
}

// ---------------------------------------------------------------------------
// tf32 GEMM: g_pre[M, FOUT] = A[M, FIN] * B[FIN, FOUT]  (unchanged from R8)
// ---------------------------------------------------------------------------
#define GM 128
#define GK 32
#define AS_STR 36
#define BS_STR 136

__global__ __launch_bounds__(256, 2) void gemm_tf32_kernel(const float* __restrict__ A,
                                                           const float* __restrict__ B) {
    __shared__ uint32_t As[GM][AS_STR];   // [m][k] tf32 bits
    __shared__ uint32_t Bs[GK][BS_STR];   // [k][n] tf32 bits

    const int tid = threadIdx.x;
    const int w = tid >> 5, l = tid & 31;
    const int wm = (w >> 1) * 32;
    const int wn = (w & 1) * 64;
    const int g = l >> 2, tg = l & 3;
    const int block_row = blockIdx.x * GM;

    float acc[2][8][4];
#pragma unroll
    for (int mi = 0; mi < 2; mi++)
#pragma unroll
        for (int ni = 0; ni < 8; ni++)
#pragma unroll
            for (int q = 0; q < 4; q++) acc[mi][ni][q] = 0.f;

    const int am = tid >> 1;
    const int akh = (tid & 1) * 16;
    const int arow = block_row + am;
    const bool aval = (arow < N_NODES);
    const float* aptr = A + (size_t)arow * FIN + akh;
    const int bk = tid >> 3;
    const int bn = (tid & 7) * 16;
    const float* bptr = B + (size_t)bk * FOUT + bn;

    for (int k0 = 0; k0 < FIN; k0 += GK) {
#pragma unroll
        for (int j = 0; j < 4; j++) {
            float4 av = make_float4(0.f, 0.f, 0.f, 0.f);
            if (aval) av = *(const float4*)(aptr + k0 + j * 4);
            uint4 tv = make_uint4(f2tf32(av.x), f2tf32(av.y), f2tf32(av.z), f2tf32(av.w));
            *(uint4*)&As[am][akh + j * 4] = tv;
        }
#pragma unroll
        for (int j = 0; j < 4; j++) {
            float4 bv = *(const float4*)(bptr + (size_t)k0 * FOUT + j * 4);
            uint4 tv = make_uint4(f2tf32(bv.x), f2tf32(bv.y), f2tf32(bv.z), f2tf32(bv.w));
            *(uint4*)&Bs[bk][bn + j * 4] = tv;
        }
        __syncthreads();

#pragma unroll
        for (int ks = 0; ks < 4; ks++) {
            const int kb = ks * 8;
            uint32_t afr[2][4], bfr[8][2];
#pragma unroll
            for (int mi = 0; mi < 2; mi++) {
                const int m = wm + mi * 16;
                afr[mi][0] = As[m + g][kb + tg];
                afr[mi][1] = As[m + g + 8][kb + tg];
                afr[mi][2] = As[m + g][kb + tg + 4];
                afr[mi][3] = As[m + g + 8][kb + tg + 4];
            }
#pragma unroll
            for (int ni = 0; ni < 8; ni++) {
                const int n = wn + ni * 8 + g;
                bfr[ni][0] = Bs[kb + tg][n];
                bfr[ni][1] = Bs[kb + tg + 4][n];
            }
#pragma unroll
            for (int mi = 0; mi < 2; mi++)
#pragma unroll
                for (int ni = 0; ni < 8; ni++)
                    mma_tf32(acc[mi][ni], afr[mi], bfr[ni]);
        }
        __syncthreads();
    }

#pragma unroll
    for (int mi = 0; mi < 2; mi++) {
        const int r0 = block_row + wm + mi * 16 + g;
#pragma unroll
        for (int ni = 0; ni < 8; ni++) {
            const int c = wn + ni * 8 + tg * 2;
            if (r0 < N_NODES)
                *(float2*)(g_pre + (size_t)r0 * FOUT + c) =
                    make_float2(acc[mi][ni][0], acc[mi][ni][1]);
            if (r0 + 8 < N_NODES)
                *(float2*)(g_pre + (size_t)(r0 + 8) * FOUT + c) =
                    make_float2(acc[mi][ni][2], acc[mi][ni][3]);
        }
    }
}

// ---------------------------------------------------------------------------
// CSR build — step 1: zero the histograms (both branches)
// ---------------------------------------------------------------------------
__global__ void zero_counts_kernel() {
    int i = blockIdx.x * blockDim.x + threadIdx.x;
    if (i < 2 * N_NODES) ((int*)g_counts)[i] = 0;
}

// step 2: histogram rows (grid.y = branch)
__global__ __launch_bounds__(256) void hist_kernel(const int* __restrict__ idx0,
                                                   const int* __restrict__ idx1, int E) {
    const int* idx = blockIdx.y ? idx1 : idx0;
    int i = blockIdx.x * blockDim.x + threadIdx.x;
    if (i >= E) return;
    int row = idx[i];
    int col = idx[E + i];
    if ((unsigned)row < N_NODES && (unsigned)col < N_NODES)
        atomicAdd(&g_counts[blockIdx.y][row], 1);
}

// step 3: exclusive scan over 50000 bins; one block per branch (blockIdx.x)
__global__ __launch_bounds__(1024) void scan_kernel() {
    const int b = blockIdx.x;
    const int t = threadIdx.x;
    const int ITEMS = (N_NODES + 1023) / 1024;   // 49
    const int start = t * ITEMS;

    int local = 0;
    for (int i = 0; i < ITEMS; i++) {
        int bin = start + i;
        if (bin < N_NODES) local += g_counts[b][bin];
    }

    __shared__ int s[1024];
    s[t] = local;
    __syncthreads();
    for (int off = 1; off < 1024; off <<= 1) {
        int v = (t >= off) ? s[t - off] : 0;
        __syncthreads();
        s[t] += v;
        __syncthreads();
    }

    int run = s[t] - local;                       // exclusive base
    for (int i = 0; i < ITEMS; i++) {
        int bin = start + i;
        if (bin < N_NODES) {
            g_rowstart[b][bin] = run;
            g_cursor[b][bin] = run;
            run += g_counts[b][bin];
        }
    }
    if (t == 1023) g_rowstart[b][N_NODES] = s[1023];
}

// step 4: scatter edges into CSR order (grid.y = branch)
__global__ __launch_bounds__(256) void scatter_kernel(const int* __restrict__ idx0,
                                                      const float* __restrict__ v0,
                                                      const int* __restrict__ idx1,
                                                      const float* __restrict__ v1, int E) {
    const int b = blockIdx.y;
    const int* idx = b ? idx1 : idx0;
    const float* vals = b ? v1 : v0;
    int i = blockIdx.x * blockDim.x + threadIdx.x;
    if (i >= E) return;
    int row = idx[i];
    int col = idx[E + i];
    if ((unsigned)row >= N_NODES || (unsigned)col >= N_NODES) return;
    int pos = atomicAdd(&g_cursor[b][row], 1);
    if (pos < MAXE) {
        g_colsorted[b][pos] = col;
        g_valsorted[b][pos] = vals[i];
    }
}

// ---------------------------------------------------------------------------
// Gather SpMM + fused bias + ReLU. One warp per (branch,row).
// Lane l accumulates float4 l of the 128-wide row in registers, writes once.
// 4-wide edge unroll for memory-level parallelism on the gathers.
// ---------------------------------------------------------------------------
__global__ __launch_bounds__(256) void spmm_csr_kernel(float* __restrict__ out,
                                                       const float* __restrict__ bias) {
    const int b = blockIdx.y;
    const int warp = threadIdx.x >> 5;
    const int lane = threadIdx.x & 31;
    const int row = blockIdx.x * 8 + warp;
    if (row >= N_NODES) return;

    const int beg = g_rowstart[b][row];
    const int end = g_rowstart[b][row + 1];
    const int* __restrict__ cols = g_colsorted[b];
    const float* __restrict__ vals = g_valsorted[b];
    const float4* __restrict__ pre4 = (const float4*)g_pre;

    float4 acc = make_float4(0.f, 0.f, 0.f, 0.f);
    int e = beg;
    for (; e + 4 <= end; e += 4) {
        int c0 = cols[e], c1 = cols[e + 1], c2 = cols[e + 2], c3 = cols[e + 3];
        float v0 = vals[e], v1 = vals[e + 1], v2 = vals[e + 2], v3 = vals[e + 3];
        float4 m0 = pre4[(size_t)c0 * 32 + lane];
        float4 m1 = pre4[(size_t)c1 * 32 + lane];
        float4 m2 = pre4[(size_t)c2 * 32 + lane];
        float4 m3 = pre4[(size_t)c3 * 32 + lane];
        acc.x += v0 * m0.x + v1 * m1.x + v2 * m2.x + v3 * m3.x;
        acc.y += v0 * m0.y + v1 * m1.y + v2 * m2.y + v3 * m3.y;
        acc.z += v0 * m0.z + v1 * m1.z + v2 * m2.z + v3 * m3.z;
        acc.w += v0 * m0.w + v1 * m1.w + v2 * m2.w + v3 * m3.w;
    }
    for (; e < end; e++) {
        int c = cols[e];
        float v = vals[e];
        float4 m = pre4[(size_t)c * 32 + lane];
        acc.x += v * m.x; acc.y += v * m.y; acc.z += v * m.z; acc.w += v * m.w;
    }

    float4 bb = ((const float4*)bias)[lane];
    acc.x = fmaxf(acc.x + bb.x, 0.f);
    acc.y = fmaxf(acc.y + bb.y, 0.f);
    acc.z = fmaxf(acc.z + bb.z, 0.f);
    acc.w = fmaxf(acc.w + bb.w, 0.f);

    float4* orow = (float4*)(out + ((size_t)b * N_NODES + row) * FOUT);
    orow[lane] = acc;
}

// ---------------------------------------------------------------------------
// Launch: gemm || csr-build  ->  gather-spmm (fused bias+relu)
// ---------------------------------------------------------------------------
extern "C" void kernel_launch(void* const* d_in, const int* in_sizes, int n_in,
                              void* d_out, int out_size) {
    const float* x     = (const float*)d_in[0];
    const int*   sidx  = (const int*)d_in[1];
    const float* svals = (const float*)d_in[2];
    const int*   oidx  = (const int*)d_in[3];
    const float* ovals = (const float*)d_in[4];
    const float* W     = (const float*)d_in[5];
    const float* bias  = (const float*)d_in[6];
    float* out = (float*)d_out;

    int E = in_sizes[2];
    if (E > MAXE) E = MAXE;

    // CSR build for both branches
    zero_counts_kernel<<<(2 * N_NODES + 255) / 256, 256>>>();
    dim3 eg((E + 255) / 256, 2);
    hist_kernel<<<eg, 256>>>(sidx, oidx, E);
    scan_kernel<<<2, 1024>>>();
    scatter_kernel<<<eg, 256>>>(sidx, svals, oidx, ovals, E);

    // Dense projection
    gemm_tf32_kernel<<<(N_NODES + GM - 1) / GM, 256>>>(x, W);

    // Gather SpMM with fused bias+ReLU (writes every output element)
    dim3 sg((N_NODES + 7) / 8, 2);
    spmm_csr_kernel<<<sg, 256>>>(out, bias);
}

// round 11
// speedup vs baseline: 1.8534x; 1.1082x over previous
#include <cuda_runtime.h>
#include <cstdint>

#define N_NODES 50000
#define FIN 512
#define FOUT 128
#define MAXE 1000000

// Static device scratch (no allocation anywhere):
__device__ float g_pre[(size_t)N_NODES * FOUT];          // 25.6 MB
__device__ int   g_counts[2][N_NODES];                   // histogram
__device__ int   g_rowstart[2][N_NODES + 1];             // CSR offsets
__device__ int   g_cursor[2][N_NODES];                   // scatter cursors
__device__ int2  g_edges[2][MAXE];                       // packed (col, val-bits), 16 MB

// ---------------------------------------------------------------------------
// helpers
// ---------------------------------------------------------------------------
__device__ __forceinline__ uint32_t f2tf32(float f) {
    uint32_t u;
    asm("cvt.rna.tf32.f32 %0, %1;" : "=r"(u) : "f"(f));
    return u;
}

__device__ __forceinline__ void mma_tf32(float* d, const uint32_t* a, const uint32_t* b) {
    asm("mma.sync.aligned.m16n8k8.row.col.f32.tf32.tf32.f32 "
        "{%0,%1,%2,%3}, {%4,%5,%6,%7}, {%8,%9}, {%0,%1,%2,%3};"
        : "+f"(d[0]), "+f"(d[1]), "+f"(d[2]), "+f"(d[3])
        : "r"(a[0]), "r"(a[1]), "r"(a[2]), "r"(a[3]), "r"(b[0]), "r"(b[1]));
}

__device__ __forceinline__ uint32_t sptr(const void* p) {
    return (uint32_t)__cvta_generic_to_shared(p);
}

__device__ __forceinline__ void cp16(uint32_t s, const void* g, int src_sz) {
    asm volatile("cp.async.ca.shared.global [%0], [%1], 16, %2;"
                 :: "r"(s), "l"(g), "r"(src_sz));
}

// ---------------------------------------------------------------------------
// tf32 GEMM, cp.async double-buffered.
// g_pre[M, FOUT] = A[M, FIN] * B[FIN, FOUT]
// Block tile M=128 x N=128, K-chunk 16, 2 stages, 256 threads = 8 warps.
// As[m][k] stride 20 -> frag banks (20g+tg)%32 bijective, conflict-free.
// Bs[k][n] stride 136 -> frag banks (8k+n)%32 bijective, conflict-free.
// tf32 cvt happens in registers after the fragment LDS (same numerics as R8).
// ---------------------------------------------------------------------------
#define GM 128
#define GK 16
#define ASTR 20
#define BSTR 136
#define NITER (FIN / GK)   // 32

__global__ __launch_bounds__(256, 2) void gemm_tf32_db(const float* __restrict__ A,
                                                       const float* __restrict__ B) {
    __shared__ float As[2][GM][ASTR];   // 2*128*20*4 = 20480 B
    __shared__ float Bs[2][GK][BSTR];   // 2*16*136*4 = 17408 B

    const int tid = threadIdx.x;
    const int w = tid >> 5, l = tid & 31;
    const int wm = (w >> 1) * 32;          // 4 warps over M
    const int wn = (w & 1) * 64;           // 2 warps over N
    const int g = l >> 2, tg = l & 3;
    const int block_row = blockIdx.x * GM;

    float acc[2][8][4];
#pragma unroll
    for (int mi = 0; mi < 2; mi++)
#pragma unroll
        for (int ni = 0; ni < 8; ni++)
#pragma unroll
            for (int q = 0; q < 4; q++) acc[mi][ni][q] = 0.f;

    // A loader: row am = tid>>1, k-offset ak = (tid&1)*8, two 16B chunks
    const int am = tid >> 1;
    const int ak = (tid & 1) * 8;
    const int arow = block_row + am;
    const int asz = (arow < N_NODES) ? 16 : 0;     // zero-fill M tail
    const float* aG = A + (size_t)arow * FIN + ak;
    // B loader: k-row bk = tid>>4, n-offset bn = (tid&15)*8, two 16B chunks
    const int bk = tid >> 4;
    const int bn = (tid & 15) * 8;
    const float* bG = B + (size_t)bk * FOUT + bn;

    const uint32_t sA0 = sptr(&As[0][am][ak]);
    const uint32_t sA1 = sptr(&As[1][am][ak]);
    const uint32_t sB0 = sptr(&Bs[0][bk][bn]);
    const uint32_t sB1 = sptr(&Bs[1][bk][bn]);

    // prologue: stage 0
    {
        const float* a0 = aG;
        const float* b0 = bG;
        cp16(sA0, a0, asz);      cp16(sA0 + 16, a0 + 4, asz);
        cp16(sB0, b0, 16);       cp16(sB0 + 16, b0 + 4, 16);
    }
    asm volatile("cp.async.commit_group;");

    for (int it = 0; it < NITER; it++) {
        const int buf = it & 1;
        if (it + 1 < NITER) {
            const float* a0 = aG + (it + 1) * GK;
            const float* b0 = bG + (size_t)(it + 1) * GK * FOUT;
            const uint32_t sa = buf ? sA0 : sA1;
            const uint32_t sb = buf ? sB0 : sB1;
            cp16(sa, a0, asz);   cp16(sa + 16, a0 + 4, asz);
            cp16(sb, b0, 16);    cp16(sb + 16, b0 + 4, 16);
        }
        asm volatile("cp.async.commit_group;");
        asm volatile("cp.async.wait_group 1;");
        __syncthreads();

#pragma unroll
        for (int ks = 0; ks < 2; ks++) {
            const int kb = ks * 8;
            uint32_t afr[2][4], bfr[8][2];
#pragma unroll
            for (int mi = 0; mi < 2; mi++) {
                const int m = wm + mi * 16;
                afr[mi][0] = f2tf32(As[buf][m + g][kb + tg]);
                afr[mi][1] = f2tf32(As[buf][m + g + 8][kb + tg]);
                afr[mi][2] = f2tf32(As[buf][m + g][kb + tg + 4]);
                afr[mi][3] = f2tf32(As[buf][m + g + 8][kb + tg + 4]);
            }
#pragma unroll
            for (int ni = 0; ni < 8; ni++) {
                const int n = wn + ni * 8 + g;
                bfr[ni][0] = f2tf32(Bs[buf][kb + tg][n]);
                bfr[ni][1] = f2tf32(Bs[buf][kb + tg + 4][n]);
            }
#pragma unroll
            for (int mi = 0; mi < 2; mi++)
#pragma unroll
                for (int ni = 0; ni < 8; ni++)
                    mma_tf32(acc[mi][ni], afr[mi], bfr[ni]);
        }
        __syncthreads();   // all warps done with buf before it's refilled
    }

#pragma unroll
    for (int mi = 0; mi < 2; mi++) {
        const int r0 = block_row + wm + mi * 16 + g;
#pragma unroll
        for (int ni = 0; ni < 8; ni++) {
            const int c = wn + ni * 8 + tg * 2;
            if (r0 < N_NODES)
                *(float2*)(g_pre + (size_t)r0 * FOUT + c) =
                    make_float2(acc[mi][ni][0], acc[mi][ni][1]);
            if (r0 + 8 < N_NODES)
                *(float2*)(g_pre + (size_t)(r0 + 8) * FOUT + c) =
                    make_float2(acc[mi][ni][2], acc[mi][ni][3]);
        }
    }
}

// ---------------------------------------------------------------------------
// CSR build — step 1: zero the histograms (both branches)
// ---------------------------------------------------------------------------
__global__ void zero_counts_kernel() {
    int i = blockIdx.x * blockDim.x + threadIdx.x;
    if (i < 2 * N_NODES) ((int*)g_counts)[i] = 0;
}

// step 2: histogram rows (grid.y = branch)
__global__ __launch_bounds__(256) void hist_kernel(const int* __restrict__ idx0,
                                                   const int* __restrict__ idx1, int E) {
    const int* idx = blockIdx.y ? idx1 : idx0;
    int i = blockIdx.x * blockDim.x + threadIdx.x;
    if (i >= E) return;
    int row = idx[i];
    int col = idx[E + i];
    if ((unsigned)row < N_NODES && (unsigned)col < N_NODES)
        atomicAdd(&g_counts[blockIdx.y][row], 1);
}

// step 3: exclusive scan over 50000 bins; one block per branch (blockIdx.x)
__global__ __launch_bounds__(1024) void scan_kernel() {
    const int b = blockIdx.x;
    const int t = threadIdx.x;
    const int ITEMS = (N_NODES + 1023) / 1024;   // 49
    const int start = t * ITEMS;

    int local = 0;
    for (int i = 0; i < ITEMS; i++) {
        int bin = start + i;
        if (bin < N_NODES) local += g_counts[b][bin];
    }

    __shared__ int s[1024];
    s[t] = local;
    __syncthreads();
    for (int off = 1; off < 1024; off <<= 1) {
        int v = (t >= off) ? s[t - off] : 0;
        __syncthreads();
        s[t] += v;
        __syncthreads();
    }

    int run = s[t] - local;                       // exclusive base
    for (int i = 0; i < ITEMS; i++) {
        int bin = start + i;
        if (bin < N_NODES) {
            g_rowstart[b][bin] = run;
            g_cursor[b][bin] = run;
            run += g_counts[b][bin];
        }
    }
    if (t == 1023) g_rowstart[b][N_NODES] = s[1023];
}

// step 4: scatter edges into CSR order, packed int2, 2 edges/thread (grid.y=branch)
__global__ __launch_bounds__(256) void scatter_kernel(const int* __restrict__ idx0,
                                                      const float* __restrict__ v0,
                                                      const int* __restrict__ idx1,
                                                      const float* __restrict__ v1, int E) {
    const int b = blockIdx.y;
    const int* idx = b ? idx1 : idx0;
    const float* vals = b ? v1 : v0;
    const int stride = gridDim.x * blockDim.x;
    int i = blockIdx.x * blockDim.x + threadIdx.x;

#pragma unroll
    for (int rep = 0; rep < 2; rep++) {
        int e = i + rep * stride;
        if (e < E) {
            int row = idx[e];
            int col = idx[E + e];
            if ((unsigned)row < N_NODES && (unsigned)col < N_NODES) {
                float v = vals[e];
                int pos = atomicAdd(&g_cursor[b][row], 1);
                if (pos < MAXE) g_edges[b][pos] = make_int2(col, __float_as_int(v));
            }
        }
    }
}

// ---------------------------------------------------------------------------
// Gather SpMM + fused bias + ReLU. One warp per (branch,row).
// Lane l accumulates float4 l of the 128-wide row; single packed int2 per edge.
// ---------------------------------------------------------------------------
__global__ __launch_bounds__(256) void spmm_csr_kernel(float* __restrict__ out,
                                                       const float* __restrict__ bias) {
    const int b = blockIdx.y;
    const int warp = threadIdx.x >> 5;
    const int lane = threadIdx.x & 31;
    const int row = blockIdx.x * 8 + warp;
    if (row >= N_NODES) return;

    const int beg = g_rowstart[b][row];
    const int end = g_rowstart[b][row + 1];
    const int2* __restrict__ edges = g_edges[b];
    const float4* __restrict__ pre4 = (const float4*)g_pre;

    float4 acc = make_float4(0.f, 0.f, 0.f, 0.f);
    int e = beg;
    for (; e + 4 <= end; e += 4) {
        int2 e0 = edges[e], e1 = edges[e + 1], e2 = edges[e + 2], e3 = edges[e + 3];
        float v0 = __int_as_float(e0.y), v1 = __int_as_float(e1.y);
        float v2 = __int_as_float(e2.y), v3 = __int_as_float(e3.y);
        float4 m0 = pre4[(size_t)e0.x * 32 + lane];
        float4 m1 = pre4[(size_t)e1.x * 32 + lane];
        float4 m2 = pre4[(size_t)e2.x * 32 + lane];
        float4 m3 = pre4[(size_t)e3.x * 32 + lane];
        acc.x += v0 * m0.x + v1 * m1.x + v2 * m2.x + v3 * m3.x;
        acc.y += v0 * m0.y + v1 * m1.y + v2 * m2.y + v3 * m3.y;
        acc.z += v0 * m0.z + v1 * m1.z + v2 * m2.z + v3 * m3.z;
        acc.w += v0 * m0.w + v1 * m1.w + v2 * m2.w + v3 * m3.w;
    }
    for (; e < end; e++) {
        int2 ed = edges[e];
        float v = __int_as_float(ed.y);
        float4 m = pre4[(size_t)ed.x * 32 + lane];
        acc.x += v * m.x; acc.y += v * m.y; acc.z += v * m.z; acc.w += v * m.w;
    }

    float4 bb = ((const float4*)bias)[lane];
    acc.x = fmaxf(acc.x + bb.x, 0.f);
    acc.y = fmaxf(acc.y + bb.y, 0.f);
    acc.z = fmaxf(acc.z + bb.z, 0.f);
    acc.w = fmaxf(acc.w + bb.w, 0.f);

    float4* orow = (float4*)(out + ((size_t)b * N_NODES + row) * FOUT);
    orow[lane] = acc;
}

// ---------------------------------------------------------------------------
// Launch: csr-build + gemm -> gather-spmm (fused bias+relu)
// ---------------------------------------------------------------------------
extern "C" void kernel_launch(void* const* d_in, const int* in_sizes, int n_in,
                              void* d_out, int out_size) {
    const float* x     = (const float*)d_in[0];
    const int*   sidx  = (const int*)d_in[1];
    const float* svals = (const float*)d_in[2];
    const int*   oidx  = (const int*)d_in[3];
    const float* ovals = (const float*)d_in[4];
    const float* W     = (const float*)d_in[5];
    const float* bias  = (const float*)d_in[6];
    float* out = (float*)d_out;

    int E = in_sizes[2];
    if (E > MAXE) E = MAXE;

    // CSR build for both branches
    zero_counts_kernel<<<(2 * N_NODES + 255) / 256, 256>>>();
    dim3 eg((E + 255) / 256, 2);
    hist_kernel<<<eg, 256>>>(sidx, oidx, E);
    scan_kernel<<<2, 1024>>>();
    dim3 eg2((E + 511) / 512, 2);          // 2 edges per thread
    scatter_kernel<<<eg2, 256>>>(sidx, svals, oidx, ovals, E);

    // Dense projection (tf32, double-buffered cp.async)
    gemm_tf32_db<<<(N_NODES + GM - 1) / GM, 256>>>(x, W);

    // Gather SpMM with fused bias+ReLU (writes every output element)
    dim3 sg((N_NODES + 7) / 8, 2);
    spmm_csr_kernel<<<sg, 256>>>(out, bias);
}